// round 9
// baseline (speedup 1.0000x reference)
#include <cuda_runtime.h>
#include <cstdint>

#define GN 16384          // N (nodes) = K (contraction) = graph size
#define NROWS 128         // B * F = 8 * 16 rows in layer-2 passes

// ---------------- scratch (static device globals; no allocations) ----------
__device__ float g_z[3][8 * GN];        // layer-1 z1, z2, z3   (1.5 MB)
__device__ float g_part[4][8 * GN];     // layer-1 k-split partials (2 MB)
__device__ float g_w[4][NROWS * GN];    // layer-2 y1, w1, w2, w3 (32 MB)

// ---------------- helpers ---------------------------------------------------
__device__ __forceinline__ uint32_t f2tf32(float f) {
    uint32_t o;
    asm("cvt.rna.tf32.f32 %0, %1;" : "=r"(o) : "f"(f));
    return o;
}

__device__ __forceinline__ void cp_async16(void* smem_dst, const void* gmem_src) {
    uint32_t d = (uint32_t)__cvta_generic_to_shared(smem_dst);
    asm volatile("cp.async.cg.shared.global [%0], [%1], 16;" :: "r"(d), "l"(gmem_src));
}
__device__ __forceinline__ void cp_commit() {
    asm volatile("cp.async.commit_group;" ::: "memory");
}

__device__ __forceinline__ void mma8(float* d, const uint32_t* a, const uint32_t* b) {
    asm volatile(
        "mma.sync.aligned.m16n8k8.row.col.f32.tf32.tf32.f32 "
        "{%0,%1,%2,%3}, {%4,%5,%6,%7}, {%8,%9}, {%0,%1,%2,%3};"
        : "+f"(d[0]), "+f"(d[1]), "+f"(d[2]), "+f"(d[3])
        : "r"(a[0]), "r"(a[1]), "r"(a[2]), "r"(a[3]), "r"(b[0]), "r"(b[1]));
}

// ---------------- layer 1: z_next[8,N] = z[8,N] * S (exact fp32, HBM-bound) -
// grid (64, 4), block 256. blockIdx.x -> 256-column tile, blockIdx.y -> K/4 chunk.
__global__ void l1_pass_kernel(const float* __restrict__ x,
                               const float* __restrict__ S, int stage) {
    __shared__ float zsm[512][8];
    const float* zin = (stage == 0) ? x : g_z[stage - 1];

    const int col = blockIdx.x * 256 + threadIdx.x;
    const int kb  = blockIdx.y * 4096;

    float acc[8];
#pragma unroll
    for (int r = 0; r < 8; r++) acc[r] = 0.f;

    for (int sc = 0; sc < 8; sc++) {
        const int mb = kb + sc * 512;
        // stage z chunk [8][512] into smem as zsm[i][r], coalesced per row
#pragma unroll
        for (int j = 0; j < 16; j++) {
            int idx = j * 256 + threadIdx.x;
            int r = idx >> 9;
            int i = idx & 511;
            zsm[i][r] = zin[r * GN + mb + i];
        }
        __syncthreads();

        const float* sp = S + (size_t)mb * GN + col;
#pragma unroll 4
        for (int i = 0; i < 512; i++) {
            float s = sp[(size_t)i * GN];
            float4 za = *(const float4*)&zsm[i][0];
            float4 zb = *(const float4*)&zsm[i][4];
            acc[0] += za.x * s;  acc[1] += za.y * s;
            acc[2] += za.z * s;  acc[3] += za.w * s;
            acc[4] += zb.x * s;  acc[5] += zb.y * s;
            acc[6] += zb.z * s;  acc[7] += zb.w * s;
        }
        __syncthreads();
    }
#pragma unroll
    for (int r = 0; r < 8; r++)
        g_part[blockIdx.y][r * GN + col] = acc[r];
}

// reduce the 4 K-chunk partials -> g_z[dst]. grid 512, block 256.
__global__ void l1_reduce_kernel(int dst) {
    int i = blockIdx.x * 256 + threadIdx.x;   // 131072 elements
    g_z[dst][i] = g_part[0][i] + g_part[1][i] + g_part[2][i] + g_part[3][i];
}

// y1[b*16+g, n] = relu(b1[g] + sum_k H1[g,k,0] * z_k[b,n]) -> g_w[0]
__global__ void y1_kernel(const float* __restrict__ x,
                          const float* __restrict__ H1,
                          const float* __restrict__ b1) {
    __shared__ float h[64], bb[16];
    if (threadIdx.x < 64) h[threadIdx.x] = H1[threadIdx.x];
    if (threadIdx.x < 16) bb[threadIdx.x] = b1[threadIdx.x];
    __syncthreads();

    int n = blockIdx.x * 256 + threadIdx.x;   // grid 64
#pragma unroll
    for (int b = 0; b < 8; b++) {
        float z0 = x[b * GN + n];
        float z1 = g_z[0][b * GN + n];
        float z2 = g_z[1][b * GN + n];
        float z3 = g_z[2][b * GN + n];
#pragma unroll
        for (int g = 0; g < 16; g++) {
            float v = bb[g] + h[g * 4 + 0] * z0 + h[g * 4 + 1] * z1
                            + h[g * 4 + 2] * z2 + h[g * 4 + 3] * z3;
            g_w[0][(b * 16 + g) * GN + n] = fmaxf(v, 0.f);
        }
    }
}

// ---------------- layer 2 GEMM: C[128,N] = A[128,K] * S  (2xTF32) ----------
// grid 256 (N/64), block 256 (8 warps in 4x2). 3-stage cp.async, Kc=16.
__global__ __launch_bounds__(256) void gemm_tf32_kernel(const float* __restrict__ S,
                                                        int src) {
    __shared__ float As[3][128][20];   // pad 20: conflict-free frag reads
    __shared__ float Bs[3][16][72];    // pad 72: conflict-free frag reads

    const float* __restrict__ A = g_w[src];
    float* __restrict__ C = g_w[src + 1];

    const int tid   = threadIdx.x;
    const int nBase = blockIdx.x * 64;
    const int warp  = tid >> 5, lane = tid & 31;
    const int wm    = warp & 3,  wn  = warp >> 2;   // 4 M-warps x 2 N-warps
    const int grp   = lane >> 2, qid = lane & 3;

    float acc[2][4][4];
#pragma unroll
    for (int a = 0; a < 2; a++)
#pragma unroll
        for (int b = 0; b < 4; b++)
#pragma unroll
            for (int c = 0; c < 4; c++) acc[a][b][c] = 0.f;

    auto load_stage = [&](int buf, int kb) {
        // A tile: 128 x 16 fp32 = 512 float4 chunks
#pragma unroll
        for (int c = tid; c < 512; c += 256) {
            int m = c >> 2, kq = c & 3;
            cp_async16(&As[buf][m][kq * 4], A + (size_t)m * GN + kb + kq * 4);
        }
        // B tile: 16 x 64 fp32 = 256 float4 chunks
        {
            int k = tid >> 4, nq = tid & 15;
            cp_async16(&Bs[buf][k][nq * 4],
                       S + (size_t)(kb + k) * GN + nBase + nq * 4);
        }
        cp_commit();
    };

    load_stage(0, 0);
    load_stage(1, 16);

    const int CH = GN / 16;   // 1024 k-chunks
    for (int it = 0; it < CH; it++) {
        if (it + 1 < CH) asm volatile("cp.async.wait_group 1;" ::: "memory");
        else             asm volatile("cp.async.wait_group 0;" ::: "memory");
        __syncthreads();
        if (it + 2 < CH) load_stage((it + 2) % 3, (it + 2) * 16);

        const int buf = it % 3;
#pragma unroll
        for (int ks = 0; ks < 2; ks++) {
            const int kk = ks * 8;
            // A fragments (plain tf32)
            uint32_t af[2][4];
#pragma unroll
            for (int mi = 0; mi < 2; mi++) {
                int rb = wm * 32 + mi * 16;
                af[mi][0] = f2tf32(As[buf][rb + grp    ][kk + qid    ]);
                af[mi][1] = f2tf32(As[buf][rb + grp + 8][kk + qid    ]);
                af[mi][2] = f2tf32(As[buf][rb + grp    ][kk + qid + 4]);
                af[mi][3] = f2tf32(As[buf][rb + grp + 8][kk + qid + 4]);
            }
            // B fragments, split into hi/lo tf32 (S represented to ~2^-22)
            uint32_t bh[4][2], bl[4][2];
#pragma unroll
            for (int ni = 0; ni < 4; ni++) {
                int cc = wn * 32 + ni * 8 + grp;
                float s0 = Bs[buf][kk + qid    ][cc];
                float s1 = Bs[buf][kk + qid + 4][cc];
                bh[ni][0] = f2tf32(s0);
                bl[ni][0] = f2tf32(s0 - __uint_as_float(bh[ni][0]));
                bh[ni][1] = f2tf32(s1);
                bl[ni][1] = f2tf32(s1 - __uint_as_float(bh[ni][1]));
            }
#pragma unroll
            for (int mi = 0; mi < 2; mi++)
#pragma unroll
                for (int ni = 0; ni < 4; ni++) {
                    mma8(acc[mi][ni], af[mi], bh[ni]);
                    mma8(acc[mi][ni], af[mi], bl[ni]);
                }
        }
    }

    // epilogue
#pragma unroll
    for (int mi = 0; mi < 2; mi++)
#pragma unroll
        for (int ni = 0; ni < 4; ni++) {
            int row  = wm * 32 + mi * 16 + grp;
            int colg = nBase + wn * 32 + ni * 8 + qid * 2;
            C[(size_t)row * GN + colg]           = acc[mi][ni][0];
            C[(size_t)row * GN + colg + 1]       = acc[mi][ni][1];
            C[(size_t)(row + 8) * GN + colg]     = acc[mi][ni][2];
            C[(size_t)(row + 8) * GN + colg + 1] = acc[mi][ni][3];
        }
}

// ---------------- epilogue: H2-einsum + relu + readout ----------------------
__global__ void out_kernel(const float* __restrict__ H2,
                           const float* __restrict__ b2,
                           const float* __restrict__ Wro,
                           const float* __restrict__ bro,
                           float* __restrict__ out) {
    __shared__ float h2[1024], wro[128], bb2[16], bbro[8];
#pragma unroll
    for (int j = 0; j < 4; j++) h2[threadIdx.x + 256 * j] = H2[threadIdx.x + 256 * j];
    if (threadIdx.x < 128) wro[threadIdx.x] = Wro[threadIdx.x];
    if (threadIdx.x < 16)  bb2[threadIdx.x] = b2[threadIdx.x];
    if (threadIdx.x < 8)   bbro[threadIdx.x] = bro[threadIdx.x];
    __syncthreads();

    int n = blockIdx.x * 256 + threadIdx.x;   // grid 64
    for (int b = 0; b < 8; b++) {
        float y2[16];
#pragma unroll
        for (int f = 0; f < 16; f++) y2[f] = bb2[f];
#pragma unroll
        for (int k = 0; k < 4; k++) {
#pragma unroll
            for (int fp = 0; fp < 16; fp++) {
                float wv = g_w[k][(b * 16 + fp) * GN + n];
#pragma unroll
                for (int f = 0; f < 16; f++)
                    y2[f] += h2[(f * 4 + k) * 16 + fp] * wv;
            }
        }
#pragma unroll
        for (int f = 0; f < 16; f++) y2[f] = fmaxf(y2[f], 0.f);
#pragma unroll
        for (int r = 0; r < 8; r++) {
            float o = bbro[r];
#pragma unroll
            for (int f = 0; f < 16; f++) o += wro[r * 16 + f] * y2[f];
            out[(b * 8 + r) * GN + n] = o;
        }
    }
}

// ---------------- launch -----------------------------------------------------
extern "C" void kernel_launch(void* const* d_in, const int* in_sizes, int n_in,
                              void* d_out, int out_size) {
    const float* x   = (const float*)d_in[0];   // [8,1,16384]
    const float* S   = (const float*)d_in[1];   // [16384,16384]
    const float* H1  = (const float*)d_in[2];   // [16,4,1]
    const float* b1  = (const float*)d_in[3];   // [16,1]
    const float* H2  = (const float*)d_in[4];   // [16,4,16]
    const float* b2  = (const float*)d_in[5];   // [16,1]
    const float* Wro = (const float*)d_in[6];   // [8,16]
    const float* bro = (const float*)d_in[7];   // [8]
    float* out = (float*)d_out;                 // [8,8,16384]

    dim3 gP(64, 4);
    // layer 1: z1 = x S, z2 = z1 S, z3 = z2 S  (exact fp32)
    l1_pass_kernel<<<gP, 256>>>(x, S, 0);
    l1_reduce_kernel<<<512, 256>>>(0);
    l1_pass_kernel<<<gP, 256>>>(x, S, 1);
    l1_reduce_kernel<<<512, 256>>>(1);
    l1_pass_kernel<<<gP, 256>>>(x, S, 2);
    l1_reduce_kernel<<<512, 256>>>(2);
    // y1 = relu(tap-combine) -> g_w[0]
    y1_kernel<<<64, 256>>>(x, H1, b1);
    // layer 2: w1 = y1 S, w2 = w1 S, w3 = w2 S  (2xTF32 tensor-core GEMM)
    gemm_tf32_kernel<<<256, 256>>>(S, 0);
    gemm_tf32_kernel<<<256, 256>>>(S, 1);
    gemm_tf32_kernel<<<256, 256>>>(S, 2);
    // epilogue: layer-2 tap-combine + relu + per-node readout
    out_kernel<<<64, 256>>>(H2, b2, Wro, bro, out);
}

// round 11
// speedup vs baseline: 1.7682x; 1.7682x over previous
#include <cuda_runtime.h>
#include <cstdint>

#define GN 16384          // N (nodes) = K (contraction) = graph size
#define NROWS 128         // B * F = 8 * 16 rows in layer-2 passes

// ---------------- scratch (static device globals; no allocations) ----------
__device__ float g_z[3][8 * GN];        // layer-1 z1, z2, z3   (1.5 MB)
__device__ float g_part[8][8 * GN];     // layer-1 k-split partials (4 MB)
__device__ float g_w[4][NROWS * GN];    // layer-2 y1, w1, w2, w3 (32 MB)

// ---------------- helpers ---------------------------------------------------
__device__ __forceinline__ uint32_t f2tf32(float f) {
    uint32_t o;
    asm("cvt.rna.tf32.f32 %0, %1;" : "=r"(o) : "f"(f));
    return o;
}

__device__ __forceinline__ void cp_async16(void* smem_dst, const void* gmem_src) {
    uint32_t d = (uint32_t)__cvta_generic_to_shared(smem_dst);
    asm volatile("cp.async.cg.shared.global [%0], [%1], 16;" :: "r"(d), "l"(gmem_src));
}
__device__ __forceinline__ void cp_commit() {
    asm volatile("cp.async.commit_group;" ::: "memory");
}

__device__ __forceinline__ void mma8(float* d, const uint32_t* a, const uint32_t* b) {
    asm volatile(
        "mma.sync.aligned.m16n8k8.row.col.f32.tf32.tf32.f32 "
        "{%0,%1,%2,%3}, {%4,%5,%6,%7}, {%8,%9}, {%0,%1,%2,%3};"
        : "+f"(d[0]), "+f"(d[1]), "+f"(d[2]), "+f"(d[3])
        : "r"(a[0]), "r"(a[1]), "r"(a[2]), "r"(a[3]), "r"(b[0]), "r"(b[1]));
}

// ---------------- layer 1: z_next[8,N] = z[8,N] * S (exact fp32, HBM-bound) -
// grid (64, 8), block 256. blockIdx.x -> 256-column tile, blockIdx.y -> K/8 chunk.
__global__ void l1_pass_kernel(const float* __restrict__ x,
                               const float* __restrict__ S, int stage) {
    __shared__ float zsm[512][8];
    const float* zin = (stage == 0) ? x : g_z[stage - 1];

    const int col = blockIdx.x * 256 + threadIdx.x;
    const int kb  = blockIdx.y * 2048;

    float acc[8];
#pragma unroll
    for (int r = 0; r < 8; r++) acc[r] = 0.f;

    for (int sc = 0; sc < 4; sc++) {
        const int mb = kb + sc * 512;
        // stage z chunk [8][512] into smem as zsm[i][r], coalesced per row
#pragma unroll
        for (int j = 0; j < 16; j++) {
            int idx = j * 256 + threadIdx.x;
            int r = idx >> 9;
            int i = idx & 511;
            zsm[i][r] = zin[r * GN + mb + i];
        }
        __syncthreads();

        const float* sp = S + (size_t)mb * GN + col;
#pragma unroll 8
        for (int i = 0; i < 512; i++) {
            float s = sp[(size_t)i * GN];
            float4 za = *(const float4*)&zsm[i][0];
            float4 zb = *(const float4*)&zsm[i][4];
            acc[0] += za.x * s;  acc[1] += za.y * s;
            acc[2] += za.z * s;  acc[3] += za.w * s;
            acc[4] += zb.x * s;  acc[5] += zb.y * s;
            acc[6] += zb.z * s;  acc[7] += zb.w * s;
        }
        __syncthreads();
    }
#pragma unroll
    for (int r = 0; r < 8; r++)
        g_part[blockIdx.y][r * GN + col] = acc[r];
}

// reduce the 8 K-chunk partials -> g_z[dst]. grid 512, block 256.
__global__ void l1_reduce_kernel(int dst) {
    int i = blockIdx.x * 256 + threadIdx.x;   // 131072 elements
    float v = 0.f;
#pragma unroll
    for (int p = 0; p < 8; p++) v += g_part[p][i];
    g_z[dst][i] = v;
}

// y1[b*16+g, n] = relu(b1[g] + sum_k H1[g,k,0] * z_k[b,n]) -> g_w[0]
__global__ void y1_kernel(const float* __restrict__ x,
                          const float* __restrict__ H1,
                          const float* __restrict__ b1) {
    __shared__ float h[64], bb[16];
    if (threadIdx.x < 64) h[threadIdx.x] = H1[threadIdx.x];
    if (threadIdx.x < 16) bb[threadIdx.x] = b1[threadIdx.x];
    __syncthreads();

    int n = blockIdx.x * 256 + threadIdx.x;   // grid 64
#pragma unroll
    for (int b = 0; b < 8; b++) {
        float z0 = x[b * GN + n];
        float z1 = g_z[0][b * GN + n];
        float z2 = g_z[1][b * GN + n];
        float z3 = g_z[2][b * GN + n];
#pragma unroll
        for (int g = 0; g < 16; g++) {
            float v = bb[g] + h[g * 4 + 0] * z0 + h[g * 4 + 1] * z1
                            + h[g * 4 + 2] * z2 + h[g * 4 + 3] * z3;
            g_w[0][(b * 16 + g) * GN + n] = fmaxf(v, 0.f);
        }
    }
}

// ---------------- layer 2 GEMM: C[128,N] = A[128,K] * S  (plain tf32) ------
// grid 128 (N/128 tiles, one full wave), block 256 (8 warps in 4x2).
// 3-stage cp.async pipeline, Kc=16. Warp tile 32x64.
#define KC     16
#define CH     (GN / KC)            // 1024 k-chunks
#define APAD   20                   // A row stride (floats): 32-bank perfect spread
#define BPAD   136                  // B row stride (floats): 8*qid+grp covers 32 banks
#define ASZ    (128 * APAD)         // floats per A stage
#define BSZ    (16 * BPAD)          // floats per B stage
#define GSMEM  (3 * (ASZ + BSZ) * 4)   // 56832 bytes

__global__ __launch_bounds__(256, 1) void gemm_tf32_kernel(const float* __restrict__ S,
                                                           int src) {
    extern __shared__ float dyn[];
    float* As = dyn;                 // [3][128][APAD]
    float* Bs = dyn + 3 * ASZ;       // [3][16][BPAD]

    const float* __restrict__ A = g_w[src];
    float* __restrict__ C = g_w[src + 1];

    const int tid   = threadIdx.x;
    const int nBase = blockIdx.x * 128;
    const int warp  = tid >> 5, lane = tid & 31;
    const int wm    = warp & 3,  wn  = warp >> 2;   // 4 M-warps x 2 N-warps
    const int grp   = lane >> 2, qid = lane & 3;

    float acc[2][8][4];
#pragma unroll
    for (int a = 0; a < 2; a++)
#pragma unroll
        for (int b = 0; b < 8; b++)
#pragma unroll
            for (int c = 0; c < 4; c++) acc[a][b][c] = 0.f;

    auto load_stage = [&](int buf, int kb) {
        float* ab = As + buf * ASZ;
        float* bb = Bs + buf * BSZ;
        // A tile: 128 x 16 fp32 = 512 float4 chunks
#pragma unroll
        for (int c = tid; c < 512; c += 256) {
            int m = c >> 2, kq = c & 3;
            cp_async16(ab + m * APAD + kq * 4, A + (size_t)m * GN + kb + kq * 4);
        }
        // B tile: 16 x 128 fp32 = 512 float4 chunks
#pragma unroll
        for (int c = tid; c < 512; c += 256) {
            int k = c >> 5, nq = c & 31;
            cp_async16(bb + k * BPAD + nq * 4,
                       S + (size_t)(kb + k) * GN + nBase + nq * 4);
        }
        cp_commit();
    };

    load_stage(0, 0);
    load_stage(1, KC);

    for (int it = 0; it < CH; it++) {
        if (it + 1 < CH) asm volatile("cp.async.wait_group 1;" ::: "memory");
        else             asm volatile("cp.async.wait_group 0;" ::: "memory");
        __syncthreads();
        if (it + 2 < CH) load_stage((it + 2) % 3, (it + 2) * KC);

        const int buf = it % 3;
        const float* ab = As + buf * ASZ;
        const float* bb = Bs + buf * BSZ;
#pragma unroll
        for (int ks = 0; ks < 2; ks++) {
            const int kk = ks * 8;
            // A fragments (plain tf32), 2 x 16-row sub-tiles
            uint32_t af[2][4];
#pragma unroll
            for (int mi = 0; mi < 2; mi++) {
                const float* ar = ab + (wm * 32 + mi * 16 + grp) * APAD + kk;
                af[mi][0] = f2tf32(ar[qid]);
                af[mi][1] = f2tf32(ar[8 * APAD + qid]);
                af[mi][2] = f2tf32(ar[qid + 4]);
                af[mi][3] = f2tf32(ar[8 * APAD + qid + 4]);
            }
            // B fragments (plain tf32), 8 x 8-col sub-tiles
            uint32_t bf[8][2];
#pragma unroll
            for (int ni = 0; ni < 8; ni++) {
                int cc = wn * 64 + ni * 8 + grp;
                bf[ni][0] = f2tf32(bb[(kk + qid) * BPAD + cc]);
                bf[ni][1] = f2tf32(bb[(kk + qid + 4) * BPAD + cc]);
            }
#pragma unroll
            for (int mi = 0; mi < 2; mi++)
#pragma unroll
                for (int ni = 0; ni < 8; ni++)
                    mma8(acc[mi][ni], af[mi], bf[ni]);
        }
    }

    // epilogue: 8B vector stores
#pragma unroll
    for (int mi = 0; mi < 2; mi++)
#pragma unroll
        for (int ni = 0; ni < 8; ni++) {
            int row  = wm * 32 + mi * 16 + grp;
            int colg = nBase + wn * 64 + ni * 8 + qid * 2;
            *(float2*)(C + (size_t)row * GN + colg) =
                make_float2(acc[mi][ni][0], acc[mi][ni][1]);
            *(float2*)(C + (size_t)(row + 8) * GN + colg) =
                make_float2(acc[mi][ni][2], acc[mi][ni][3]);
        }
}

// ---------------- epilogue: H2-einsum + relu + readout ----------------------
__global__ void out_kernel(const float* __restrict__ H2,
                           const float* __restrict__ b2,
                           const float* __restrict__ Wro,
                           const float* __restrict__ bro,
                           float* __restrict__ out) {
    __shared__ float h2[1024], wro[128], bb2[16], bbro[8];
#pragma unroll
    for (int j = 0; j < 4; j++) h2[threadIdx.x + 256 * j] = H2[threadIdx.x + 256 * j];
    if (threadIdx.x < 128) wro[threadIdx.x] = Wro[threadIdx.x];
    if (threadIdx.x < 16)  bb2[threadIdx.x] = b2[threadIdx.x];
    if (threadIdx.x < 8)   bbro[threadIdx.x] = bro[threadIdx.x];
    __syncthreads();

    int n = blockIdx.x * 256 + threadIdx.x;   // grid 64
    for (int b = 0; b < 8; b++) {
        float y2[16];
#pragma unroll
        for (int f = 0; f < 16; f++) y2[f] = bb2[f];
#pragma unroll
        for (int k = 0; k < 4; k++) {
#pragma unroll
            for (int fp = 0; fp < 16; fp++) {
                float wv = g_w[k][(b * 16 + fp) * GN + n];
#pragma unroll
                for (int f = 0; f < 16; f++)
                    y2[f] += h2[(f * 4 + k) * 16 + fp] * wv;
            }
        }
#pragma unroll
        for (int f = 0; f < 16; f++) y2[f] = fmaxf(y2[f], 0.f);
#pragma unroll
        for (int r = 0; r < 8; r++) {
            float o = bbro[r];
#pragma unroll
            for (int f = 0; f < 16; f++) o += wro[r * 16 + f] * y2[f];
            out[(b * 8 + r) * GN + n] = o;
        }
    }
}

// ---------------- launch -----------------------------------------------------
extern "C" void kernel_launch(void* const* d_in, const int* in_sizes, int n_in,
                              void* d_out, int out_size) {
    const float* x   = (const float*)d_in[0];   // [8,1,16384]
    const float* S   = (const float*)d_in[1];   // [16384,16384]
    const float* H1  = (const float*)d_in[2];   // [16,4,1]
    const float* b1  = (const float*)d_in[3];   // [16,1]
    const float* H2  = (const float*)d_in[4];   // [16,4,16]
    const float* b2  = (const float*)d_in[5];   // [16,1]
    const float* Wro = (const float*)d_in[6];   // [8,16]
    const float* bro = (const float*)d_in[7];   // [8]
    float* out = (float*)d_out;                 // [8,8,16384]

    cudaFuncSetAttribute(gemm_tf32_kernel,
                         cudaFuncAttributeMaxDynamicSharedMemorySize, GSMEM);

    dim3 gP(64, 8);
    // layer 1: z1 = x S, z2 = z1 S, z3 = z2 S  (exact fp32)
    l1_pass_kernel<<<gP, 256>>>(x, S, 0);
    l1_reduce_kernel<<<512, 256>>>(0);
    l1_pass_kernel<<<gP, 256>>>(x, S, 1);
    l1_reduce_kernel<<<512, 256>>>(1);
    l1_pass_kernel<<<gP, 256>>>(x, S, 2);
    l1_reduce_kernel<<<512, 256>>>(2);
    // y1 = relu(tap-combine) -> g_w[0]
    y1_kernel<<<64, 256>>>(x, H1, b1);
    // layer 2: w1 = y1 S, w2 = w1 S, w3 = w2 S  (plain tf32 tensor-core GEMM)
    gemm_tf32_kernel<<<128, 256, GSMEM>>>(S, 0);
    gemm_tf32_kernel<<<128, 256, GSMEM>>>(S, 1);
    gemm_tf32_kernel<<<128, 256, GSMEM>>>(S, 2);
    // epilogue: layer-2 tap-combine + relu + per-node readout
    out_kernel<<<64, 256>>>(H2, b2, Wro, bro, out);
}

// round 12
// speedup vs baseline: 2.1684x; 1.2263x over previous
#include <cuda_runtime.h>
#include <cstdint>

#define GN 16384          // N (nodes) = K (contraction) = graph size
#define NROWS 128         // B * F = 8 * 16 rows in layer-2 passes

// ---------------- scratch (static device globals; no allocations) ----------
__device__ float g_z[3][8 * GN];        // layer-1 z1, z2, z3   (1.5 MB)
__device__ float g_part[8][8 * GN];     // layer-1 k-split partials (4 MB)
__device__ float g_w[4][NROWS * GN];    // layer-2 y1, w1, w2, w3 (32 MB)
__device__ float g_gp[2][NROWS * GN];   // layer-2 GEMM k-split partials (16 MB)

// ---------------- helpers ---------------------------------------------------
__device__ __forceinline__ void cp_async16(void* smem_dst, const void* gmem_src) {
    uint32_t d = (uint32_t)__cvta_generic_to_shared(smem_dst);
    asm volatile("cp.async.cg.shared.global [%0], [%1], 16;" :: "r"(d), "l"(gmem_src));
}
__device__ __forceinline__ void cp_commit() {
    asm volatile("cp.async.commit_group;" ::: "memory");
}

__device__ __forceinline__ void mma8(float* d, const uint32_t* a, const uint32_t* b) {
    asm volatile(
        "mma.sync.aligned.m16n8k8.row.col.f32.tf32.tf32.f32 "
        "{%0,%1,%2,%3}, {%4,%5,%6,%7}, {%8,%9}, {%0,%1,%2,%3};"
        : "+f"(d[0]), "+f"(d[1]), "+f"(d[2]), "+f"(d[3])
        : "r"(a[0]), "r"(a[1]), "r"(a[2]), "r"(a[3]), "r"(b[0]), "r"(b[1]));
}

// ---------------- layer 1: z_next[8,N] = z[8,N] * S (exact fp32, HBM-bound) -
// grid (64, 8), block 256. blockIdx.x -> 256-column tile, blockIdx.y -> K/8 chunk.
__global__ void l1_pass_kernel(const float* __restrict__ x,
                               const float* __restrict__ S, int stage) {
    __shared__ float zsm[512][8];
    const float* zin = (stage == 0) ? x : g_z[stage - 1];

    const int col = blockIdx.x * 256 + threadIdx.x;
    const int kb  = blockIdx.y * 2048;

    float acc[8];
#pragma unroll
    for (int r = 0; r < 8; r++) acc[r] = 0.f;

    for (int sc = 0; sc < 4; sc++) {
        const int mb = kb + sc * 512;
#pragma unroll
        for (int j = 0; j < 16; j++) {
            int idx = j * 256 + threadIdx.x;
            int r = idx >> 9;
            int i = idx & 511;
            zsm[i][r] = zin[r * GN + mb + i];
        }
        __syncthreads();

        const float* sp = S + (size_t)mb * GN + col;
#pragma unroll 8
        for (int i = 0; i < 512; i++) {
            float s = sp[(size_t)i * GN];
            float4 za = *(const float4*)&zsm[i][0];
            float4 zb = *(const float4*)&zsm[i][4];
            acc[0] += za.x * s;  acc[1] += za.y * s;
            acc[2] += za.z * s;  acc[3] += za.w * s;
            acc[4] += zb.x * s;  acc[5] += zb.y * s;
            acc[6] += zb.z * s;  acc[7] += zb.w * s;
        }
        __syncthreads();
    }
#pragma unroll
    for (int r = 0; r < 8; r++)
        g_part[blockIdx.y][r * GN + col] = acc[r];
}

// reduce the 8 K-chunk partials -> g_z[dst]. grid 512, block 256.
__global__ void l1_reduce_kernel(int dst) {
    int i = blockIdx.x * 256 + threadIdx.x;   // 131072 elements
    float v = 0.f;
#pragma unroll
    for (int p = 0; p < 8; p++) v += g_part[p][i];
    g_z[dst][i] = v;
}

// y1[b*16+g, n] = relu(b1[g] + sum_k H1[g,k,0] * z_k[b,n]) -> g_w[0]
__global__ void y1_kernel(const float* __restrict__ x,
                          const float* __restrict__ H1,
                          const float* __restrict__ b1) {
    __shared__ float h[64], bb[16];
    if (threadIdx.x < 64) h[threadIdx.x] = H1[threadIdx.x];
    if (threadIdx.x < 16) bb[threadIdx.x] = b1[threadIdx.x];
    __syncthreads();

    int n = blockIdx.x * 256 + threadIdx.x;   // grid 64
#pragma unroll
    for (int b = 0; b < 8; b++) {
        float z0 = x[b * GN + n];
        float z1 = g_z[0][b * GN + n];
        float z2 = g_z[1][b * GN + n];
        float z3 = g_z[2][b * GN + n];
#pragma unroll
        for (int g = 0; g < 16; g++) {
            float v = bb[g] + h[g * 4 + 0] * z0 + h[g * 4 + 1] * z1
                            + h[g * 4 + 2] * z2 + h[g * 4 + 3] * z3;
            g_w[0][(b * 16 + g) * GN + n] = fmaxf(v, 0.f);
        }
    }
}

// ---------------- layer 2 GEMM: C[128,N] = A[128,K] * S  (tf32, raw bits) ---
// grid (128, 2): x -> 128-col tile, y -> K/2 split (8192 each).
// block 256 (8 warps in 4x2), 3-stage cp.async pipeline, Kc=16, warp tile 32x64.
// Fragments feed raw fp32 bits to HMMA (tf32 = top 19 bits of fp32 layout;
// HW truncates low mantissa — no cvt needed).
#define KC     16
#define KSPL   8192
#define CH2    (KSPL / KC)          // 512 k-chunks per split
#define APAD   20                   // A row stride (floats): 32-bank perfect spread
#define BPAD   136                  // B row stride (floats): 8*qid+grp covers 32 banks
#define ASZ    (128 * APAD)
#define BSZ    (16 * BPAD)
#define GSMEM  (3 * (ASZ + BSZ) * 4)   // 56832 bytes

__global__ __launch_bounds__(256) void gemm_tf32_kernel(const float* __restrict__ S,
                                                        int src) {
    extern __shared__ float dyn[];
    float* As = dyn;                 // [3][128][APAD]
    float* Bs = dyn + 3 * ASZ;       // [3][16][BPAD]

    const float* __restrict__ A = g_w[src];
    float* __restrict__ C = g_gp[blockIdx.y];

    const int tid   = threadIdx.x;
    const int nBase = blockIdx.x * 128;
    const int kBase = blockIdx.y * KSPL;
    const int warp  = tid >> 5, lane = tid & 31;
    const int wm    = warp & 3,  wn  = warp >> 2;   // 4 M-warps x 2 N-warps
    const int grp   = lane >> 2, qid = lane & 3;

    float acc[2][8][4];
#pragma unroll
    for (int a = 0; a < 2; a++)
#pragma unroll
        for (int b = 0; b < 8; b++)
#pragma unroll
            for (int c = 0; c < 4; c++) acc[a][b][c] = 0.f;

    auto load_stage = [&](int buf, int kb) {
        float* ab = As + buf * ASZ;
        float* bb = Bs + buf * BSZ;
        // A tile: 128 x 16 fp32 = 512 float4 chunks
#pragma unroll
        for (int c = tid; c < 512; c += 256) {
            int m = c >> 2, kq = c & 3;
            cp_async16(ab + m * APAD + kq * 4, A + (size_t)m * GN + kb + kq * 4);
        }
        // B tile: 16 x 128 fp32 = 512 float4 chunks
#pragma unroll
        for (int c = tid; c < 512; c += 256) {
            int k = c >> 5, nq = c & 31;
            cp_async16(bb + k * BPAD + nq * 4,
                       S + (size_t)(kb + k) * GN + nBase + nq * 4);
        }
        cp_commit();
    };

    load_stage(0, kBase);
    load_stage(1, kBase + KC);

    for (int it = 0; it < CH2; it++) {
        if (it + 1 < CH2) asm volatile("cp.async.wait_group 1;" ::: "memory");
        else              asm volatile("cp.async.wait_group 0;" ::: "memory");
        __syncthreads();
        if (it + 2 < CH2) load_stage((it + 2) % 3, kBase + (it + 2) * KC);

        const int buf = it % 3;
        const uint32_t* ab = (const uint32_t*)(As + buf * ASZ);
        const uint32_t* bb = (const uint32_t*)(Bs + buf * BSZ);
#pragma unroll
        for (int ks = 0; ks < 2; ks++) {
            const int kk = ks * 8;
            // A fragments: raw fp32 bits (HW truncates to tf32)
            uint32_t af[2][4];
#pragma unroll
            for (int mi = 0; mi < 2; mi++) {
                const uint32_t* ar = ab + (wm * 32 + mi * 16 + grp) * APAD + kk;
                af[mi][0] = ar[qid];
                af[mi][1] = ar[8 * APAD + qid];
                af[mi][2] = ar[qid + 4];
                af[mi][3] = ar[8 * APAD + qid + 4];
            }
            // B fragments: raw fp32 bits
            uint32_t bf[8][2];
#pragma unroll
            for (int ni = 0; ni < 8; ni++) {
                int cc = wn * 64 + ni * 8 + grp;
                bf[ni][0] = bb[(kk + qid) * BPAD + cc];
                bf[ni][1] = bb[(kk + qid + 4) * BPAD + cc];
            }
#pragma unroll
            for (int mi = 0; mi < 2; mi++)
#pragma unroll
                for (int ni = 0; ni < 8; ni++)
                    mma8(acc[mi][ni], af[mi], bf[ni]);
        }
    }

    // epilogue: 8B vector stores into this split's partial buffer
#pragma unroll
    for (int mi = 0; mi < 2; mi++)
#pragma unroll
        for (int ni = 0; ni < 8; ni++) {
            int row  = wm * 32 + mi * 16 + grp;
            int colg = nBase + wn * 64 + ni * 8 + qid * 2;
            *(float2*)(C + (size_t)row * GN + colg) =
                make_float2(acc[mi][ni][0], acc[mi][ni][1]);
            *(float2*)(C + (size_t)(row + 8) * GN + colg) =
                make_float2(acc[mi][ni][2], acc[mi][ni][3]);
        }
}

// combine the 2 K-split partials -> g_w[dst]. grid 2048, block 256 (float4).
__global__ void gemm_combine_kernel(int dst) {
    int i = blockIdx.x * 256 + threadIdx.x;   // 524288 float4s
    float4 a = ((const float4*)g_gp[0])[i];
    float4 b = ((const float4*)g_gp[1])[i];
    float4 v = make_float4(a.x + b.x, a.y + b.y, a.z + b.z, a.w + b.w);
    ((float4*)g_w[dst])[i] = v;
}

// ---------------- epilogue: H2-einsum + relu + readout ----------------------
__global__ void out_kernel(const float* __restrict__ H2,
                           const float* __restrict__ b2,
                           const float* __restrict__ Wro,
                           const float* __restrict__ bro,
                           float* __restrict__ out) {
    __shared__ float h2[1024], wro[128], bb2[16], bbro[8];
#pragma unroll
    for (int j = 0; j < 4; j++) h2[threadIdx.x + 256 * j] = H2[threadIdx.x + 256 * j];
    if (threadIdx.x < 128) wro[threadIdx.x] = Wro[threadIdx.x];
    if (threadIdx.x < 16)  bb2[threadIdx.x] = b2[threadIdx.x];
    if (threadIdx.x < 8)   bbro[threadIdx.x] = bro[threadIdx.x];
    __syncthreads();

    int n = blockIdx.x * 256 + threadIdx.x;   // grid 64
    for (int b = 0; b < 8; b++) {
        float y2[16];
#pragma unroll
        for (int f = 0; f < 16; f++) y2[f] = bb2[f];
#pragma unroll
        for (int k = 0; k < 4; k++) {
#pragma unroll
            for (int fp = 0; fp < 16; fp++) {
                float wv = g_w[k][(b * 16 + fp) * GN + n];
#pragma unroll
                for (int f = 0; f < 16; f++)
                    y2[f] += h2[(f * 4 + k) * 16 + fp] * wv;
            }
        }
#pragma unroll
        for (int f = 0; f < 16; f++) y2[f] = fmaxf(y2[f], 0.f);
#pragma unroll
        for (int r = 0; r < 8; r++) {
            float o = bbro[r];
#pragma unroll
            for (int f = 0; f < 16; f++) o += wro[r * 16 + f] * y2[f];
            out[(b * 8 + r) * GN + n] = o;
        }
    }
}

// ---------------- launch -----------------------------------------------------
extern "C" void kernel_launch(void* const* d_in, const int* in_sizes, int n_in,
                              void* d_out, int out_size) {
    const float* x   = (const float*)d_in[0];   // [8,1,16384]
    const float* S   = (const float*)d_in[1];   // [16384,16384]
    const float* H1  = (const float*)d_in[2];   // [16,4,1]
    const float* b1  = (const float*)d_in[3];   // [16,1]
    const float* H2  = (const float*)d_in[4];   // [16,4,16]
    const float* b2  = (const float*)d_in[5];   // [16,1]
    const float* Wro = (const float*)d_in[6];   // [8,16]
    const float* bro = (const float*)d_in[7];   // [8]
    float* out = (float*)d_out;                 // [8,8,16384]

    cudaFuncSetAttribute(gemm_tf32_kernel,
                         cudaFuncAttributeMaxDynamicSharedMemorySize, GSMEM);

    dim3 gP(64, 8);
    // layer 1: z1 = x S, z2 = z1 S, z3 = z2 S  (exact fp32)
    l1_pass_kernel<<<gP, 256>>>(x, S, 0);
    l1_reduce_kernel<<<512, 256>>>(0);
    l1_pass_kernel<<<gP, 256>>>(x, S, 1);
    l1_reduce_kernel<<<512, 256>>>(1);
    l1_pass_kernel<<<gP, 256>>>(x, S, 2);
    l1_reduce_kernel<<<512, 256>>>(2);
    // y1 = relu(tap-combine) -> g_w[0]
    y1_kernel<<<64, 256>>>(x, H1, b1);
    // layer 2: w1 = y1 S, w2 = w1 S, w3 = w2 S  (tf32 tensor-core, K-split 2)
    dim3 gG(128, 2);
    gemm_tf32_kernel<<<gG, 256, GSMEM>>>(S, 0);
    gemm_combine_kernel<<<2048, 256>>>(1);
    gemm_tf32_kernel<<<gG, 256, GSMEM>>>(S, 1);
    gemm_combine_kernel<<<2048, 256>>>(2);
    gemm_tf32_kernel<<<gG, 256, GSMEM>>>(S, 2);
    gemm_combine_kernel<<<2048, 256>>>(3);
    // epilogue: layer-2 tap-combine + relu + per-node readout
    out_kernel<<<64, 256>>>(H2, b2, Wro, bro, out);
}

// round 14
// speedup vs baseline: 2.2129x; 1.0205x over previous
#include <cuda_runtime.h>
#include <cstdint>

#define GN 16384          // N (nodes) = K (contraction) = graph size
#define NROWS 128         // B * F = 8 * 16 rows in layer-2 passes

// ---------------- scratch (static device globals; no allocations) ----------
__device__ float g_z[3][8 * GN];        // layer-1 z1, z2, z3   (1.5 MB)
__device__ float g_part[8][8 * GN];     // layer-1 k-split partials (4 MB)
__device__ float g_w[4][NROWS * GN];    // layer-2 y1, w1, w2, w3 (32 MB)
__device__ float g_gp16[16][NROWS * GN]; // layer-2 GEMM k-slice partials (128 MB)

// ---------------- helpers ---------------------------------------------------
__device__ __forceinline__ void cp_async16(void* smem_dst, const void* gmem_src) {
    uint32_t d = (uint32_t)__cvta_generic_to_shared(smem_dst);
    asm volatile("cp.async.cg.shared.global [%0], [%1], 16;" :: "r"(d), "l"(gmem_src));
}
__device__ __forceinline__ void cp_commit() {
    asm volatile("cp.async.commit_group;" ::: "memory");
}

__device__ __forceinline__ void mma8(float* d, const uint32_t* a, const uint32_t* b) {
    asm volatile(
        "mma.sync.aligned.m16n8k8.row.col.f32.tf32.tf32.f32 "
        "{%0,%1,%2,%3}, {%4,%5,%6,%7}, {%8,%9}, {%0,%1,%2,%3};"
        : "+f"(d[0]), "+f"(d[1]), "+f"(d[2]), "+f"(d[3])
        : "r"(a[0]), "r"(a[1]), "r"(a[2]), "r"(a[3]), "r"(b[0]), "r"(b[1]));
}

// ---------------- layer 1: z_next[8,N] = z[8,N] * S (exact fp32, HBM-bound) -
// grid (32, 8), block 256. blockIdx.x -> 512-column tile (2 cols/thread,
// float2 loads), blockIdx.y -> K/8 chunk.
__global__ void l1_pass_kernel(const float* __restrict__ x,
                               const float* __restrict__ S, int stage) {
    __shared__ float zsm[512][8];
    const float* zin = (stage == 0) ? x : g_z[stage - 1];

    const int col = (blockIdx.x * 256 + threadIdx.x) * 2;
    const int kb  = blockIdx.y * 2048;

    float acc[16];   // [r][0..1]
#pragma unroll
    for (int r = 0; r < 16; r++) acc[r] = 0.f;

    for (int sc = 0; sc < 4; sc++) {
        const int mb = kb + sc * 512;
        // stage z chunk [8][512] into smem as zsm[i][r], coalesced per row
#pragma unroll
        for (int j = 0; j < 16; j++) {
            int idx = j * 256 + threadIdx.x;
            int r = idx >> 9;
            int i = idx & 511;
            zsm[i][r] = zin[r * GN + mb + i];
        }
        __syncthreads();

        const float2* sp = (const float2*)(S + (size_t)mb * GN + col);
#pragma unroll 8
        for (int i = 0; i < 512; i++) {
            float2 s = sp[(size_t)i * (GN / 2)];
            float4 za = *(const float4*)&zsm[i][0];
            float4 zb = *(const float4*)&zsm[i][4];
            acc[0]  += za.x * s.x;  acc[1]  += za.x * s.y;
            acc[2]  += za.y * s.x;  acc[3]  += za.y * s.y;
            acc[4]  += za.z * s.x;  acc[5]  += za.z * s.y;
            acc[6]  += za.w * s.x;  acc[7]  += za.w * s.y;
            acc[8]  += zb.x * s.x;  acc[9]  += zb.x * s.y;
            acc[10] += zb.y * s.x;  acc[11] += zb.y * s.y;
            acc[12] += zb.z * s.x;  acc[13] += zb.z * s.y;
            acc[14] += zb.w * s.x;  acc[15] += zb.w * s.y;
        }
        __syncthreads();
    }
#pragma unroll
    for (int r = 0; r < 8; r++)
        *(float2*)&g_part[blockIdx.y][r * GN + col] =
            make_float2(acc[r * 2], acc[r * 2 + 1]);
}

// reduce the 8 K-chunk partials -> g_z[dst]. grid 512, block 256.
__global__ void l1_reduce_kernel(int dst) {
    int i = blockIdx.x * 256 + threadIdx.x;   // 131072 elements
    float v = 0.f;
#pragma unroll
    for (int p = 0; p < 8; p++) v += g_part[p][i];
    g_z[dst][i] = v;
}

// y1[b*16+g, n] = relu(b1[g] + sum_k H1[g,k,0] * z_k[b,n]) -> g_w[0]
__global__ void y1_kernel(const float* __restrict__ x,
                          const float* __restrict__ H1,
                          const float* __restrict__ b1) {
    __shared__ float h[64], bb[16];
    if (threadIdx.x < 64) h[threadIdx.x] = H1[threadIdx.x];
    if (threadIdx.x < 16) bb[threadIdx.x] = b1[threadIdx.x];
    __syncthreads();

    int n = blockIdx.x * 256 + threadIdx.x;   // grid 64
#pragma unroll
    for (int b = 0; b < 8; b++) {
        float z0 = x[b * GN + n];
        float z1 = g_z[0][b * GN + n];
        float z2 = g_z[1][b * GN + n];
        float z3 = g_z[2][b * GN + n];
#pragma unroll
        for (int g = 0; g < 16; g++) {
            float v = bb[g] + h[g * 4 + 0] * z0 + h[g * 4 + 1] * z1
                            + h[g * 4 + 2] * z2 + h[g * 4 + 3] * z3;
            g_w[0][(b * 16 + g) * GN + n] = fmaxf(v, 0.f);
        }
    }
}

// ---------------- layer 2 GEMM: C[128,N] = A[128,K] * S  (tf32, raw bits) ---
// Persistent balanced grid: 296 workers (2 CTAs/SM on 148 SMs), 2048 work
// items = (128 n-tiles) x (16 K-slices of 1024). Worker w takes items
// w, w+296, ... (static, deterministic, disjoint writes to 16 partials).
// Block 256 (8 warps in 4x2), 3-stage cp.async pipeline, Kc=16, warp 32x64.
// Fragments feed raw fp32 bits to HMMA (tf32 = top 19 bits of fp32 layout).
#define KC     16
#define KSLICE 1024
#define NCHUNK (KSLICE / KC)        // 64 k-chunks per item
#define NITEMS 2048
#define NWORK  296
#define APAD   20                   // A row stride (floats): 32-bank perfect spread
#define BPAD   136                  // B row stride (floats): 8*qid+grp covers 32 banks
#define ASZ    (128 * APAD)
#define BSZ    (16 * BPAD)
#define GSMEM  (3 * (ASZ + BSZ) * 4)   // 56832 bytes

__global__ __launch_bounds__(256, 2) void gemm_tf32_kernel(const float* __restrict__ S,
                                                           int src) {
    extern __shared__ float dyn[];
    float* As = dyn;                 // [3][128][APAD]
    float* Bs = dyn + 3 * ASZ;       // [3][16][BPAD]

    const float* __restrict__ A = g_w[src];

    const int tid   = threadIdx.x;
    const int warp  = tid >> 5, lane = tid & 31;
    const int wm    = warp & 3,  wn  = warp >> 2;   // 4 M-warps x 2 N-warps
    const int grp   = lane >> 2, qid = lane & 3;

    auto load_stage = [&](int buf, int kb, int nBase) {
        float* ab = As + buf * ASZ;
        float* bb = Bs + buf * BSZ;
        // A tile: 128 x 16 fp32 = 512 float4 chunks
#pragma unroll
        for (int c = tid; c < 512; c += 256) {
            int m = c >> 2, kq = c & 3;
            cp_async16(ab + m * APAD + kq * 4, A + (size_t)m * GN + kb + kq * 4);
        }
        // B tile: 16 x 128 fp32 = 512 float4 chunks
#pragma unroll
        for (int c = tid; c < 512; c += 256) {
            int k = c >> 5, nq = c & 31;
            cp_async16(bb + k * BPAD + nq * 4,
                       S + (size_t)(kb + k) * GN + nBase + nq * 4);
        }
        cp_commit();
    };

    for (int item = blockIdx.x; item < NITEMS; item += NWORK) {
        const int tile  = item & 127;
        const int ksl   = item >> 7;          // 0..15
        const int nBase = tile * 128;
        const int kBase = ksl * KSLICE;
        float* __restrict__ C = g_gp16[ksl];

        float acc[2][8][4];
#pragma unroll
        for (int a = 0; a < 2; a++)
#pragma unroll
            for (int b = 0; b < 8; b++)
#pragma unroll
                for (int c = 0; c < 4; c++) acc[a][b][c] = 0.f;

        load_stage(0, kBase, nBase);
        load_stage(1, kBase + KC, nBase);

        for (int it = 0; it < NCHUNK; it++) {
            if (it + 1 < NCHUNK) asm volatile("cp.async.wait_group 1;" ::: "memory");
            else                 asm volatile("cp.async.wait_group 0;" ::: "memory");
            __syncthreads();
            if (it + 2 < NCHUNK) load_stage((it + 2) % 3, kBase + (it + 2) * KC, nBase);

            const int buf = it % 3;
            const uint32_t* ab = (const uint32_t*)(As + buf * ASZ);
            const uint32_t* bb = (const uint32_t*)(Bs + buf * BSZ);
#pragma unroll
            for (int ks = 0; ks < 2; ks++) {
                const int kk = ks * 8;
                // A fragments: raw fp32 bits (HW truncates to tf32)
                uint32_t af[2][4];
#pragma unroll
                for (int mi = 0; mi < 2; mi++) {
                    const uint32_t* ar = ab + (wm * 32 + mi * 16 + grp) * APAD + kk;
                    af[mi][0] = ar[qid];
                    af[mi][1] = ar[8 * APAD + qid];
                    af[mi][2] = ar[qid + 4];
                    af[mi][3] = ar[8 * APAD + qid + 4];
                }
                // B fragments: raw fp32 bits
                uint32_t bf[8][2];
#pragma unroll
                for (int ni = 0; ni < 8; ni++) {
                    int cc = wn * 64 + ni * 8 + grp;
                    bf[ni][0] = bb[(kk + qid) * BPAD + cc];
                    bf[ni][1] = bb[(kk + qid + 4) * BPAD + cc];
                }
#pragma unroll
                for (int mi = 0; mi < 2; mi++)
#pragma unroll
                    for (int ni = 0; ni < 8; ni++)
                        mma8(acc[mi][ni], af[mi], bf[ni]);
            }
        }
        // all cp.async drained (wait_group 0 at it=NCHUNK-1); guard smem reuse
        __syncthreads();

        // epilogue: 8B vector stores into this item's k-slice partial buffer
#pragma unroll
        for (int mi = 0; mi < 2; mi++)
#pragma unroll
            for (int ni = 0; ni < 8; ni++) {
                int row  = wm * 32 + mi * 16 + grp;
                int colg = nBase + wn * 64 + ni * 8 + qid * 2;
                *(float2*)(C + (size_t)row * GN + colg) =
                    make_float2(acc[mi][ni][0], acc[mi][ni][1]);
                *(float2*)(C + (size_t)(row + 8) * GN + colg) =
                    make_float2(acc[mi][ni][2], acc[mi][ni][3]);
            }
    }
}

// combine the 16 K-slice partials -> g_w[dst]. grid 2048, block 256 (float4).
__global__ void gemm_combine_kernel(int dst) {
    int i = blockIdx.x * 256 + threadIdx.x;   // 524288 float4s
    float4 v = make_float4(0.f, 0.f, 0.f, 0.f);
#pragma unroll
    for (int p = 0; p < 16; p++) {
        float4 a = ((const float4*)g_gp16[p])[i];
        v.x += a.x; v.y += a.y; v.z += a.z; v.w += a.w;
    }
    ((float4*)g_w[dst])[i] = v;
}

// ---------------- epilogue: H2-einsum + relu + readout ----------------------
__global__ void out_kernel(const float* __restrict__ H2,
                           const float* __restrict__ b2,
                           const float* __restrict__ Wro,
                           const float* __restrict__ bro,
                           float* __restrict__ out) {
    __shared__ float h2[1024], wro[128], bb2[16], bbro[8];
#pragma unroll
    for (int j = 0; j < 4; j++) h2[threadIdx.x + 256 * j] = H2[threadIdx.x + 256 * j];
    if (threadIdx.x < 128) wro[threadIdx.x] = Wro[threadIdx.x];
    if (threadIdx.x < 16)  bb2[threadIdx.x] = b2[threadIdx.x];
    if (threadIdx.x < 8)   bbro[threadIdx.x] = bro[threadIdx.x];
    __syncthreads();

    int n = blockIdx.x * 256 + threadIdx.x;   // grid 64
    for (int b = 0; b < 8; b++) {
        float y2[16];
#pragma unroll
        for (int f = 0; f < 16; f++) y2[f] = bb2[f];
#pragma unroll
        for (int k = 0; k < 4; k++) {
#pragma unroll
            for (int fp = 0; fp < 16; fp++) {
                float wv = g_w[k][(b * 16 + fp) * GN + n];
#pragma unroll
                for (int f = 0; f < 16; f++)
                    y2[f] += h2[(f * 4 + k) * 16 + fp] * wv;
            }
        }
#pragma unroll
        for (int f = 0; f < 16; f++) y2[f] = fmaxf(y2[f], 0.f);
#pragma unroll
        for (int r = 0; r < 8; r++) {
            float o = bbro[r];
#pragma unroll
            for (int f = 0; f < 16; f++) o += wro[r * 16 + f] * y2[f];
            out[(b * 8 + r) * GN + n] = o;
        }
    }
}

// ---------------- launch -----------------------------------------------------
extern "C" void kernel_launch(void* const* d_in, const int* in_sizes, int n_in,
                              void* d_out, int out_size) {
    const float* x   = (const float*)d_in[0];   // [8,1,16384]
    const float* S   = (const float*)d_in[1];   // [16384,16384]
    const float* H1  = (const float*)d_in[2];   // [16,4,1]
    const float* b1  = (const float*)d_in[3];   // [16,1]
    const float* H2  = (const float*)d_in[4];   // [16,4,16]
    const float* b2  = (const float*)d_in[5];   // [16,1]
    const float* Wro = (const float*)d_in[6];   // [8,16]
    const float* bro = (const float*)d_in[7];   // [8]
    float* out = (float*)d_out;                 // [8,8,16384]

    cudaFuncSetAttribute(gemm_tf32_kernel,
                         cudaFuncAttributeMaxDynamicSharedMemorySize, GSMEM);

    dim3 gP(32, 8);
    // layer 1: z1 = x S, z2 = z1 S, z3 = z2 S  (exact fp32)
    l1_pass_kernel<<<gP, 256>>>(x, S, 0);
    l1_reduce_kernel<<<512, 256>>>(0);
    l1_pass_kernel<<<gP, 256>>>(x, S, 1);
    l1_reduce_kernel<<<512, 256>>>(1);
    l1_pass_kernel<<<gP, 256>>>(x, S, 2);
    l1_reduce_kernel<<<512, 256>>>(2);
    // y1 = relu(tap-combine) -> g_w[0]
    y1_kernel<<<64, 256>>>(x, H1, b1);
    // layer 2: w1 = y1 S, w2 = w1 S, w3 = w2 S
    // (tf32 tensor-core, persistent balanced grid + 16-way K-slice partials)
    gemm_tf32_kernel<<<NWORK, 256, GSMEM>>>(S, 0);
    gemm_combine_kernel<<<2048, 256>>>(1);
    gemm_tf32_kernel<<<NWORK, 256, GSMEM>>>(S, 1);
    gemm_combine_kernel<<<2048, 256>>>(2);
    gemm_tf32_kernel<<<NWORK, 256, GSMEM>>>(S, 2);
    gemm_combine_kernel<<<2048, 256>>>(3);
    // epilogue: layer-2 tap-combine + relu + per-node readout
    out_kernel<<<64, 256>>>(H2, b2, Wro, bro, out);
}

// round 15
// speedup vs baseline: 2.9585x; 1.3369x over previous
#include <cuda_runtime.h>
#include <cuda_bf16.h>
#include <cstdint>

#define GN 16384          // N (nodes) = K (contraction) = graph size
#define NROWS 128         // B * F = 8 * 16 rows in layer-2 passes

// ---------------- scratch (static device globals; no allocations) ----------
__device__ float g_z[3][8 * GN];           // layer-1 z1, z2, z3   (1.5 MB)
__device__ float g_part[8][8 * GN];        // layer-1 k-split partials (4 MB)
__device__ float g_w[4][NROWS * GN];       // layer-2 y1, w1, w2, w3 fp32 (32 MB)
__device__ float g_gp16[16][NROWS * GN];   // layer-2 GEMM k-slice partials (128 MB)
__device__ __nv_bfloat16 g_Sb[(size_t)GN * GN];  // S in bf16 (512 MB)
__device__ __nv_bfloat16 g_ab[3][NROWS * GN];    // GEMM A operands bf16 (12 MB)

// ---------------- helpers ---------------------------------------------------
__device__ __forceinline__ void cp_async16(void* smem_dst, const void* gmem_src) {
    uint32_t d = (uint32_t)__cvta_generic_to_shared(smem_dst);
    asm volatile("cp.async.cg.shared.global [%0], [%1], 16;" :: "r"(d), "l"(gmem_src));
}
__device__ __forceinline__ void cp_commit() {
    asm volatile("cp.async.commit_group;" ::: "memory");
}

__device__ __forceinline__ void ldsm4(uint32_t* r, uint32_t addr) {
    asm volatile("ldmatrix.sync.aligned.m8n8.x4.shared.b16 {%0,%1,%2,%3}, [%4];"
                 : "=r"(r[0]), "=r"(r[1]), "=r"(r[2]), "=r"(r[3]) : "r"(addr));
}
__device__ __forceinline__ void ldsm4t(uint32_t* r, uint32_t addr) {
    asm volatile("ldmatrix.sync.aligned.m8n8.x4.trans.shared.b16 {%0,%1,%2,%3}, [%4];"
                 : "=r"(r[0]), "=r"(r[1]), "=r"(r[2]), "=r"(r[3]) : "r"(addr));
}

__device__ __forceinline__ void mma16(float* d, const uint32_t* a, const uint32_t* b) {
    asm volatile(
        "mma.sync.aligned.m16n8k16.row.col.f32.bf16.bf16.f32 "
        "{%0,%1,%2,%3}, {%4,%5,%6,%7}, {%8,%9}, {%0,%1,%2,%3};"
        : "+f"(d[0]), "+f"(d[1]), "+f"(d[2]), "+f"(d[3])
        : "r"(a[0]), "r"(a[1]), "r"(a[2]), "r"(a[3]), "r"(b[0]), "r"(b[1]));
}

// ---------------- layer 1 pass 1: z1 partials = x * S, and S -> bf16 --------
// grid (32, 8), block 256. Also emits g_Sb (each (row,col) visited once).
__global__ void l1_pass1_kernel(const float* __restrict__ x,
                                const float* __restrict__ S) {
    __shared__ float zsm[512][8];
    const int col = (blockIdx.x * 256 + threadIdx.x) * 2;
    const int kb  = blockIdx.y * 2048;

    float acc[16];
#pragma unroll
    for (int r = 0; r < 16; r++) acc[r] = 0.f;

    for (int sc = 0; sc < 4; sc++) {
        const int mb = kb + sc * 512;
#pragma unroll
        for (int j = 0; j < 16; j++) {
            int idx = j * 256 + threadIdx.x;
            int r = idx >> 9;
            int i = idx & 511;
            zsm[i][r] = x[r * GN + mb + i];
        }
        __syncthreads();

        const float2* sp = (const float2*)(S + (size_t)mb * GN + col);
#pragma unroll 8
        for (int i = 0; i < 512; i++) {
            float2 s = sp[(size_t)i * (GN / 2)];
            // emit bf16 S (round-to-nearest)
            *(__nv_bfloat162*)(g_Sb + (size_t)(mb + i) * GN + col) =
                __float22bfloat162_rn(s);
            float4 za = *(const float4*)&zsm[i][0];
            float4 zb = *(const float4*)&zsm[i][4];
            acc[0]  += za.x * s.x;  acc[1]  += za.x * s.y;
            acc[2]  += za.y * s.x;  acc[3]  += za.y * s.y;
            acc[4]  += za.z * s.x;  acc[5]  += za.z * s.y;
            acc[6]  += za.w * s.x;  acc[7]  += za.w * s.y;
            acc[8]  += zb.x * s.x;  acc[9]  += zb.x * s.y;
            acc[10] += zb.y * s.x;  acc[11] += zb.y * s.y;
            acc[12] += zb.z * s.x;  acc[13] += zb.z * s.y;
            acc[14] += zb.w * s.x;  acc[15] += zb.w * s.y;
        }
        __syncthreads();
    }
#pragma unroll
    for (int r = 0; r < 8; r++)
        *(float2*)&g_part[blockIdx.y][r * GN + col] =
            make_float2(acc[r * 2], acc[r * 2 + 1]);
}

// ---------------- layer 1 passes 2,3: z_next = z * S_bf16 -------------------
__global__ void l1_pass_bf_kernel(int stage) {
    __shared__ float zsm[512][8];
    const float* zin = g_z[stage - 1];
    const int col = (blockIdx.x * 256 + threadIdx.x) * 2;
    const int kb  = blockIdx.y * 2048;

    float acc[16];
#pragma unroll
    for (int r = 0; r < 16; r++) acc[r] = 0.f;

    for (int sc = 0; sc < 4; sc++) {
        const int mb = kb + sc * 512;
#pragma unroll
        for (int j = 0; j < 16; j++) {
            int idx = j * 256 + threadIdx.x;
            int r = idx >> 9;
            int i = idx & 511;
            zsm[i][r] = zin[r * GN + mb + i];
        }
        __syncthreads();

        const __nv_bfloat162* sp =
            (const __nv_bfloat162*)(g_Sb + (size_t)mb * GN + col);
#pragma unroll 8
        for (int i = 0; i < 512; i++) {
            float2 s = __bfloat1622float2(sp[(size_t)i * (GN / 2)]);
            float4 za = *(const float4*)&zsm[i][0];
            float4 zb = *(const float4*)&zsm[i][4];
            acc[0]  += za.x * s.x;  acc[1]  += za.x * s.y;
            acc[2]  += za.y * s.x;  acc[3]  += za.y * s.y;
            acc[4]  += za.z * s.x;  acc[5]  += za.z * s.y;
            acc[6]  += za.w * s.x;  acc[7]  += za.w * s.y;
            acc[8]  += zb.x * s.x;  acc[9]  += zb.x * s.y;
            acc[10] += zb.y * s.x;  acc[11] += zb.y * s.y;
            acc[12] += zb.z * s.x;  acc[13] += zb.z * s.y;
            acc[14] += zb.w * s.x;  acc[15] += zb.w * s.y;
        }
        __syncthreads();
    }
#pragma unroll
    for (int r = 0; r < 8; r++)
        *(float2*)&g_part[blockIdx.y][r * GN + col] =
            make_float2(acc[r * 2], acc[r * 2 + 1]);
}

// reduce the 8 K-chunk partials -> g_z[dst]. grid 512, block 256.
__global__ void l1_reduce_kernel(int dst) {
    int i = blockIdx.x * 256 + threadIdx.x;   // 131072 elements
    float v = 0.f;
#pragma unroll
    for (int p = 0; p < 8; p++) v += g_part[p][i];
    g_z[dst][i] = v;
}

// y1 = relu(tap-combine) -> g_w[0] (fp32) and g_ab[0] (bf16 GEMM operand)
__global__ void y1_kernel(const float* __restrict__ x,
                          const float* __restrict__ H1,
                          const float* __restrict__ b1) {
    __shared__ float h[64], bb[16];
    if (threadIdx.x < 64) h[threadIdx.x] = H1[threadIdx.x];
    if (threadIdx.x < 16) bb[threadIdx.x] = b1[threadIdx.x];
    __syncthreads();

    int n = blockIdx.x * 256 + threadIdx.x;   // grid 64
#pragma unroll
    for (int b = 0; b < 8; b++) {
        float z0 = x[b * GN + n];
        float z1 = g_z[0][b * GN + n];
        float z2 = g_z[1][b * GN + n];
        float z3 = g_z[2][b * GN + n];
#pragma unroll
        for (int g = 0; g < 16; g++) {
            float v = bb[g] + h[g * 4 + 0] * z0 + h[g * 4 + 1] * z1
                            + h[g * 4 + 2] * z2 + h[g * 4 + 3] * z3;
            v = fmaxf(v, 0.f);
            g_w[0][(b * 16 + g) * GN + n] = v;
            g_ab[0][(b * 16 + g) * GN + n] = __float2bfloat16(v);
        }
    }
}

// ---------------- layer 2 GEMM: C[128,N] = A[128,K] * S  (bf16 HMMA) -------
// Persistent balanced grid: 296 workers (2 CTAs/SM), 2048 items =
// (128 n-tiles) x (16 K-slices of 1024). Block 256 (8 warps, 4m x 2n),
// warp tile 32x64, CTA tile 128x128, Kc=32, 3-stage cp.async pipeline.
// A via ldmatrix.x4 (row-major), B = S via ldmatrix.x4.trans from [k][n].
#define KC     32
#define KSLICE 1024
#define NCHUNK (KSLICE / KC)        // 32 chunks per item
#define NITEMS 2048
#define NWORK  296
#define APITCH 40                   // halves; 80B rows -> 8 distinct 16B groups
#define BPITCH 136                  // halves; 272B rows -> 8 distinct 16B groups
#define ASZH   (128 * APITCH)       // 5120 halves / stage (10240 B)
#define BSZH   (32 * BPITCH)        // 4352 halves / stage (8704 B)
#define GSMEM  (3 * (ASZH + BSZH) * 2)   // 56832 B

__global__ __launch_bounds__(256, 2) void gemm_bf16_kernel(int src) {
    extern __shared__ __nv_bfloat16 dynb[];
    __nv_bfloat16* As = dynb;               // [3][128][APITCH]
    __nv_bfloat16* Bs = dynb + 3 * ASZH;    // [3][32][BPITCH]

    const __nv_bfloat16* __restrict__ Ag = g_ab[src];
    const __nv_bfloat16* __restrict__ Sb = g_Sb;

    const int tid  = threadIdx.x;
    const int warp = tid >> 5, lane = tid & 31;
    const int wm   = warp & 3,  wn  = warp >> 2;   // 4 M-warps x 2 N-warps
    const int grp  = lane >> 2, qid = lane & 3;

    const uint32_t aBase = (uint32_t)__cvta_generic_to_shared(As);
    const uint32_t bBase = (uint32_t)__cvta_generic_to_shared(Bs);

    // ldmatrix per-thread address components
    const int rowA  = wm * 32 + (lane & 7) + 8 * ((lane >> 3) & 1);
    const int colAq = 8 * (lane >> 4);
    const int rowBq = (lane & 7) + 8 * ((lane >> 3) & 1);
    const int colB  = wn * 64 + 8 * (lane >> 4);

    auto load_stage = [&](int buf, int kb, int nBase) {
        __nv_bfloat16* ab = As + buf * ASZH;
        __nv_bfloat16* bb = Bs + buf * BSZH;
        // A tile: 128 rows x 32 halves (64 B) = 512 x 16B
#pragma unroll
        for (int c = tid; c < 512; c += 256) {
            int m = c >> 2, kq = (c & 3) * 8;
            cp_async16(ab + m * APITCH + kq, Ag + (size_t)m * GN + kb + kq);
        }
        // B tile: 32 rows x 128 halves (256 B) = 512 x 16B
#pragma unroll
        for (int c = tid; c < 512; c += 256) {
            int k = c >> 4, nq = (c & 15) * 8;
            cp_async16(bb + k * BPITCH + nq, Sb + (size_t)(kb + k) * GN + nBase + nq);
        }
        cp_commit();
    };

    for (int item = blockIdx.x; item < NITEMS; item += NWORK) {
        const int tile  = item & 127;
        const int ksl   = item >> 7;          // 0..15
        const int nBase = tile * 128;
        const int kBase = ksl * KSLICE;
        float* __restrict__ C = g_gp16[ksl];

        float acc[2][8][4];
#pragma unroll
        for (int a = 0; a < 2; a++)
#pragma unroll
            for (int b = 0; b < 8; b++)
#pragma unroll
                for (int c = 0; c < 4; c++) acc[a][b][c] = 0.f;

        load_stage(0, kBase, nBase);
        load_stage(1, kBase + KC, nBase);

        for (int it = 0; it < NCHUNK; it++) {
            if (it + 1 < NCHUNK) asm volatile("cp.async.wait_group 1;" ::: "memory");
            else                 asm volatile("cp.async.wait_group 0;" ::: "memory");
            __syncthreads();
            if (it + 2 < NCHUNK) load_stage((it + 2) % 3, kBase + (it + 2) * KC, nBase);

            const int buf = it % 3;
            const uint32_t aB = aBase + buf * (ASZH * 2);
            const uint32_t bB = bBase + buf * (BSZH * 2);
#pragma unroll
            for (int ks = 0; ks < 2; ks++) {
                const int kk = ks * 16;
                uint32_t af[2][4];
#pragma unroll
                for (int mi = 0; mi < 2; mi++)
                    ldsm4(af[mi],
                          aB + (uint32_t)(((rowA + mi * 16) * APITCH + colAq + kk) * 2));
                uint32_t bf[4][4];
#pragma unroll
                for (int j = 0; j < 4; j++)
                    ldsm4t(bf[j],
                           bB + (uint32_t)(((rowBq + kk) * BPITCH + colB + j * 16) * 2));
#pragma unroll
                for (int mi = 0; mi < 2; mi++)
#pragma unroll
                    for (int ni = 0; ni < 8; ni++)
                        mma16(acc[mi][ni], af[mi], &bf[ni >> 1][(ni & 1) * 2]);
            }
        }
        // all cp.async drained; guard smem reuse across items
        __syncthreads();

        // epilogue: 8B vector stores into this item's k-slice partial buffer
#pragma unroll
        for (int mi = 0; mi < 2; mi++)
#pragma unroll
            for (int ni = 0; ni < 8; ni++) {
                int row  = wm * 32 + mi * 16 + grp;
                int colg = nBase + wn * 64 + ni * 8 + qid * 2;
                *(float2*)(C + (size_t)row * GN + colg) =
                    make_float2(acc[mi][ni][0], acc[mi][ni][1]);
                *(float2*)(C + (size_t)(row + 8) * GN + colg) =
                    make_float2(acc[mi][ni][2], acc[mi][ni][3]);
            }
    }
}

// combine 16 K-slice partials -> g_w[dst] fp32 (+ bf16 A for next GEMM).
__global__ void gemm_combine_kernel(int dst) {
    int i = blockIdx.x * 256 + threadIdx.x;   // 524288 float4s
    float4 v = make_float4(0.f, 0.f, 0.f, 0.f);
#pragma unroll
    for (int p = 0; p < 16; p++) {
        float4 a = ((const float4*)g_gp16[p])[i];
        v.x += a.x; v.y += a.y; v.z += a.z; v.w += a.w;
    }
    ((float4*)g_w[dst])[i] = v;
    if (dst < 3) {
        __nv_bfloat162 lo = __float22bfloat162_rn(make_float2(v.x, v.y));
        __nv_bfloat162 hi = __float22bfloat162_rn(make_float2(v.z, v.w));
        ((__nv_bfloat162*)g_ab[dst])[i * 2]     = lo;
        ((__nv_bfloat162*)g_ab[dst])[i * 2 + 1] = hi;
    }
}

// ---------------- epilogue: H2-einsum + relu + readout ----------------------
__global__ void out_kernel(const float* __restrict__ H2,
                           const float* __restrict__ b2,
                           const float* __restrict__ Wro,
                           const float* __restrict__ bro,
                           float* __restrict__ out) {
    __shared__ float h2[1024], wro[128], bb2[16], bbro[8];
#pragma unroll
    for (int j = 0; j < 4; j++) h2[threadIdx.x + 256 * j] = H2[threadIdx.x + 256 * j];
    if (threadIdx.x < 128) wro[threadIdx.x] = Wro[threadIdx.x];
    if (threadIdx.x < 16)  bb2[threadIdx.x] = b2[threadIdx.x];
    if (threadIdx.x < 8)   bbro[threadIdx.x] = bro[threadIdx.x];
    __syncthreads();

    int n = blockIdx.x * 256 + threadIdx.x;   // grid 64
    for (int b = 0; b < 8; b++) {
        float y2[16];
#pragma unroll
        for (int f = 0; f < 16; f++) y2[f] = bb2[f];
#pragma unroll
        for (int k = 0; k < 4; k++) {
#pragma unroll
            for (int fp = 0; fp < 16; fp++) {
                float wv = g_w[k][(b * 16 + fp) * GN + n];
#pragma unroll
                for (int f = 0; f < 16; f++)
                    y2[f] += h2[(f * 4 + k) * 16 + fp] * wv;
            }
        }
#pragma unroll
        for (int f = 0; f < 16; f++) y2[f] = fmaxf(y2[f], 0.f);
#pragma unroll
        for (int r = 0; r < 8; r++) {
            float o = bbro[r];
#pragma unroll
            for (int f = 0; f < 16; f++) o += wro[r * 16 + f] * y2[f];
            out[(b * 8 + r) * GN + n] = o;
        }
    }
}

// ---------------- launch -----------------------------------------------------
extern "C" void kernel_launch(void* const* d_in, const int* in_sizes, int n_in,
                              void* d_out, int out_size) {
    const float* x   = (const float*)d_in[0];   // [8,1,16384]
    const float* S   = (const float*)d_in[1];   // [16384,16384]
    const float* H1  = (const float*)d_in[2];   // [16,4,1]
    const float* b1  = (const float*)d_in[3];   // [16,1]
    const float* H2  = (const float*)d_in[4];   // [16,4,16]
    const float* b2  = (const float*)d_in[5];   // [16,1]
    const float* Wro = (const float*)d_in[6];   // [8,16]
    const float* bro = (const float*)d_in[7];   // [8]
    float* out = (float*)d_out;                 // [8,8,16384]

    cudaFuncSetAttribute(gemm_bf16_kernel,
                         cudaFuncAttributeMaxDynamicSharedMemorySize, GSMEM);

    dim3 gP(32, 8);
    // layer 1: z1 = x S (fp32 S, emits bf16 S), z2/z3 via bf16 S
    l1_pass1_kernel<<<gP, 256>>>(x, S);
    l1_reduce_kernel<<<512, 256>>>(0);
    l1_pass_bf_kernel<<<gP, 256>>>(1);
    l1_reduce_kernel<<<512, 256>>>(1);
    l1_pass_bf_kernel<<<gP, 256>>>(2);
    l1_reduce_kernel<<<512, 256>>>(2);
    // y1 = relu(tap-combine) -> g_w[0] + g_ab[0]
    y1_kernel<<<64, 256>>>(x, H1, b1);
    // layer 2: w1 = y1 S, w2 = w1 S, w3 = w2 S  (bf16 HMMA, persistent grid)
    gemm_bf16_kernel<<<NWORK, 256, GSMEM>>>(0);
    gemm_combine_kernel<<<2048, 256>>>(1);
    gemm_bf16_kernel<<<NWORK, 256, GSMEM>>>(1);
    gemm_combine_kernel<<<2048, 256>>>(2);
    gemm_bf16_kernel<<<NWORK, 256, GSMEM>>>(2);
    gemm_combine_kernel<<<2048, 256>>>(3);
    // epilogue: layer-2 tap-combine + relu + per-node readout
    out_kernel<<<64, 256>>>(H2, b2, Wro, bro, out);
}